// round 13
// baseline (speedup 1.0000x reference)
#include <cuda_runtime.h>
#include <cuda_bf16.h>
#include <cstdint>

// ============================================================
// RankingLoss: persistent FP8(e4m3) mma.sync GEMM with per-row/
// per-class scaling, cp.async ring, fused hinge epilogue +
// in-kernel final reduce. gt exact fp32.
// loss = sum_{b,c: tc[c]!=label[b]} max(1 + pred_b·sigc_c - gt_b, 0)
// ============================================================

#define MAX_B   16384
#define DDIM    256
#define CPAD    2048
#define PGRID   148

__device__ float g_gt[MAX_B];
__device__ float g_partial[CPAD];
__device__ float g_sigT[CPAD * DDIM];                       // sig^T fp32 [c][d]
__device__ __align__(256) unsigned char g_predq[MAX_B * DDIM]; // pred e4m3
__device__ __align__(256) unsigned char g_sgq[CPAD * DDIM];    // gathered sig e4m3
__device__ float g_sa[MAX_B];                               // pred row scales (max/448)
__device__ float g_sb[CPAD];                                // class scales
__device__ int g_tcs[CPAD];                                 // class ids (-1 pad)
__device__ unsigned g_done;

// ---------------- transpose sig fp32: [d][c] -> [c][d] ----------------
__global__ void transpose_sig_kernel(const float* __restrict__ sig, int C) {
    __shared__ float t[32][33];
    int cb = blockIdx.x * 32, db = blockIdx.y * 32;
    int tx = threadIdx.x & 31, ty = threadIdx.x >> 5;
    #pragma unroll
    for (int i = 0; i < 32; i += 8) {
        int d = db + ty + i, c = cb + tx;
        t[ty + i][tx] = (c < C) ? sig[(size_t)d * C + c] : 0.f;
    }
    __syncthreads();
    #pragma unroll
    for (int i = 0; i < 32; i += 8) {
        int c = cb + ty + i, d = db + tx;
        if (c < CPAD) g_sigT[(size_t)c * DDIM + d] = t[tx][ty + i];
    }
    if (blockIdx.x == 0 && blockIdx.y == 0 && threadIdx.x == 0) g_done = 0u;
}

// ---------------- fp8 pack helpers ----------------
__device__ __forceinline__ float warp_max(float v) {
    #pragma unroll
    for (int o = 16; o > 0; o >>= 1) v = fmaxf(v, __shfl_xor_sync(0xffffffffu, v, o));
    return v;
}
// pack 8 floats (scaled) -> 8 e4m3 bytes; cvt d, x, y => d = {hi=x, lo=y}
__device__ __forceinline__ uint2 pack8_e4m3(float inv, float4 a, float4 b) {
    unsigned short h0, h1, h2, h3;
    asm("cvt.rn.satfinite.e4m3x2.f32 %0, %1, %2;" : "=h"(h0) : "f"(a.y * inv), "f"(a.x * inv));
    asm("cvt.rn.satfinite.e4m3x2.f32 %0, %1, %2;" : "=h"(h1) : "f"(a.w * inv), "f"(a.z * inv));
    asm("cvt.rn.satfinite.e4m3x2.f32 %0, %1, %2;" : "=h"(h2) : "f"(b.y * inv), "f"(b.x * inv));
    asm("cvt.rn.satfinite.e4m3x2.f32 %0, %1, %2;" : "=h"(h3) : "f"(b.w * inv), "f"(b.z * inv));
    uint2 r;
    r.x = (uint32_t)h0 | ((uint32_t)h1 << 16);
    r.y = (uint32_t)h2 | ((uint32_t)h3 << 16);
    return r;
}

// ---------------- fused prep: quantize pred + exact gt (rows); gather+quantize sig (classes) ----------------
__global__ void prep_all_kernel(const float* __restrict__ pred,
                                const int* __restrict__ label,
                                const int* __restrict__ tclass,
                                int B, int C) {
    const int tid = threadIdx.x, lane = tid & 31, wid = tid >> 5;
    const int rowBlocks = B / 8;

    if ((int)blockIdx.x < rowBlocks) {
        int b = blockIdx.x * 8 + wid;
        const float4* p4 = (const float4*)pred + (size_t)b * 64;
        float4 v0 = p4[lane * 2], v1 = p4[lane * 2 + 1];
        float m = fmaxf(fmaxf(fmaxf(fabsf(v0.x), fabsf(v0.y)), fmaxf(fabsf(v0.z), fabsf(v0.w))),
                        fmaxf(fmaxf(fabsf(v1.x), fabsf(v1.y)), fmaxf(fabsf(v1.z), fabsf(v1.w))));
        m = warp_max(m);
        float inv = (m > 0.f) ? 448.f / m : 0.f;
        *(uint2*)&g_predq[(size_t)b * DDIM + lane * 8] = pack8_e4m3(inv, v0, v1);
        // exact gt
        int lb = label[b];
        const float4* s4 = (const float4*)g_sigT + (size_t)lb * 64;
        float4 c0 = s4[lane * 2], c1 = s4[lane * 2 + 1];
        float s = v0.x*c0.x + v0.y*c0.y + v0.z*c0.z + v0.w*c0.w
                + v1.x*c1.x + v1.y*c1.y + v1.z*c1.z + v1.w*c1.w;
        #pragma unroll
        for (int o = 16; o > 0; o >>= 1) s += __shfl_down_sync(0xffffffffu, s, o);
        if (lane == 0) { g_gt[b] = s; g_sa[b] = m / 448.f; }
    } else {
        int c = ((int)blockIdx.x - rowBlocks) * 8 + wid;
        if (c < C) {
            int cls = tclass[c];
            const float4* s4 = (const float4*)g_sigT + (size_t)cls * 64;
            float4 v0 = s4[lane * 2], v1 = s4[lane * 2 + 1];
            float m = fmaxf(fmaxf(fmaxf(fabsf(v0.x), fabsf(v0.y)), fmaxf(fabsf(v0.z), fabsf(v0.w))),
                            fmaxf(fmaxf(fabsf(v1.x), fabsf(v1.y)), fmaxf(fabsf(v1.z), fabsf(v1.w))));
            m = warp_max(m);
            float inv = (m > 0.f) ? 448.f / m : 0.f;
            *(uint2*)&g_sgq[(size_t)c * DDIM + lane * 8] = pack8_e4m3(inv, v0, v1);
            if (lane == 0) { g_sb[c] = m / 448.f; g_tcs[c] = cls; }
        } else if (c < CPAD) {
            uint2 z; z.x = 0u; z.y = 0u;
            *(uint2*)&g_sgq[(size_t)c * DDIM + lane * 8] = z;
            if (lane == 0) { g_sb[c] = 0.f; g_tcs[c] = -1; }
        }
    }
}

// ---------------- persistent FP8 MMA GEMM + hinge + final reduce ----------------
// Tile 128 rows x 256 classes; k=256 bytes in 2 chunks of 128B.
// 512 threads (16 warps, 4m x 4n, warp 32x64).
// Ring: 4 slots x (A 16KB + B 32KB) = 192KB.
#define SLOT_SZ  49152
#define B_SUB    16384
#define RED_OFF  196608
#define SMEM_TOTAL 198656

__device__ __forceinline__ uint32_t smem_u32(const void* p) {
    uint32_t a;
    asm("{ .reg .u64 t; cvta.to.shared.u64 t, %1; cvt.u32.u64 %0, t; }" : "=r"(a) : "l"(p));
    return a;
}

#define CP_ASYNC16(dst, src) \
    asm volatile("cp.async.cg.shared.global [%0], [%1], 16;" :: "r"(dst), "l"(src) : "memory")
#define CP_COMMIT() asm volatile("cp.async.commit_group;" ::: "memory")
#define CP_WAIT2()  asm volatile("cp.async.wait_group 2;" ::: "memory")

#define LDMX4(r0, r1, r2, r3, a) \
    asm volatile("ldmatrix.sync.aligned.m8n8.x4.shared.b16 {%0,%1,%2,%3}, [%4];" \
        : "=r"(r0), "=r"(r1), "=r"(r2), "=r"(r3) : "r"(a))

#define MMAF8(c, A, b0, b1) \
    asm volatile("mma.sync.aligned.m16n8k32.row.col.f32.e4m3.e4m3.f32 " \
        "{%0,%1,%2,%3}, {%4,%5,%6,%7}, {%8,%9}, {%0,%1,%2,%3};" \
        : "+f"((c)[0]), "+f"((c)[1]), "+f"((c)[2]), "+f"((c)[3]) \
        : "r"((A)[0]), "r"((A)[1]), "r"((A)[2]), "r"((A)[3]), "r"(b0), "r"(b1))

// Fill one 128-byte k-chunk (chk in {0,1}) of tile ft into ring slot fs.
__device__ __forceinline__ void fill_chunk(uint32_t sb, int ft, int chk, int fs, int tid) {
    const int r0f = (ft >> 3) * 128;
    const int c0f = (ft & 7) * 256;
    const uint32_t slot = sb + (uint32_t)fs * SLOT_SZ;
    #pragma unroll
    for (int i = 0; i < 2; i++) {              // A: 128 rows x 8 x 16B
        int op = tid + i * 512;
        int row = op >> 3, u = op & 7;
        uint32_t dst = slot + (uint32_t)row * 128u + (uint32_t)((u ^ (row & 7)) << 4);
        size_t src = __cvta_generic_to_global(&g_predq[(size_t)(r0f + row) * DDIM + chk * 128 + u * 16]);
        CP_ASYNC16(dst, src);
    }
    #pragma unroll
    for (int i = 0; i < 4; i++) {              // B: 256 rows x 8 x 16B
        int op = tid + i * 512;
        int row = op >> 3, u = op & 7;
        uint32_t dst = slot + B_SUB + (uint32_t)row * 128u + (uint32_t)((u ^ (row & 7)) << 4);
        size_t src = __cvta_generic_to_global(&g_sgq[(size_t)(c0f + row) * DDIM + chk * 128 + u * 16]);
        CP_ASYNC16(dst, src);
    }
}

__global__ __launch_bounds__(512, 1)
void hinge_mma_kernel(const int* __restrict__ label, int nt, float* __restrict__ out) {
    extern __shared__ char smem[];
    const uint32_t sb = smem_u32(smem);
    const int tid = threadIdx.x, lane = tid & 31, wid = tid >> 5;
    const int bid = blockIdx.x;

    const int wm = (wid & 3) * 32;
    const int wn = (wid >> 2) * 64;
    const int lrow = lane & 15;
    const uint32_t u0 = (uint32_t)(lane >> 4);
    const uint32_t xr = (uint32_t)(lane & 7);

    float acc[2][8][4];
    #pragma unroll
    for (int mi = 0; mi < 2; mi++)
        #pragma unroll
        for (int ni = 0; ni < 8; ni++)
            #pragma unroll
            for (int q = 0; q < 4; q++) acc[mi][ni][q] = 0.f;

    // ---- prologue: fill 3 chunks ahead ----
    int ft = bid, fch = 0, fs = 0;
    #pragma unroll
    for (int p = 0; p < 3; p++) {
        if (ft < nt) fill_chunk(sb, ft, fch, fs, tid);
        CP_COMMIT();
        fs = (fs + 1) & 3;
        if (++fch == 2) { fch = 0; ft += PGRID; }
    }
    int cs = 0;

    for (int tile = bid; tile < nt; tile += PGRID) {
        #pragma unroll
        for (int ch = 0; ch < 2; ch++) {
            CP_WAIT2();
            __syncthreads();
            if (ft < nt) fill_chunk(sb, ft, fch, fs, tid);
            CP_COMMIT();
            fs = (fs + 1) & 3;
            if (++fch == 2) { fch = 0; ft += PGRID; }
            // ---- MMA on slot cs: 4 k32-steps ----
            const uint32_t slot = sb + (uint32_t)cs * SLOT_SZ;
            uint32_t baseA0 = slot + (uint32_t)(wm + lrow) * 128u;
            uint32_t baseA1 = baseA0 + 16u * 128u;
            uint32_t baseB0 = slot + B_SUB + (uint32_t)(wn + lrow) * 128u;
            uint32_t baseB1 = baseB0 + 16u * 128u;
            uint32_t baseB2 = baseB0 + 32u * 128u;
            uint32_t baseB3 = baseB0 + 48u * 128u;
            #pragma unroll
            for (int kk = 0; kk < 4; kk++) {
                const uint32_t t = (((uint32_t)(2 * kk) + u0) ^ xr) << 4;
                uint32_t a[2][4];
                LDMX4(a[0][0], a[0][1], a[0][2], a[0][3], baseA0 + t);
                LDMX4(a[1][0], a[1][1], a[1][2], a[1][3], baseA1 + t);
                uint32_t b[8][2];
                {
                    uint32_t q0, q1, q2, q3;
                    LDMX4(q0, q1, q2, q3, baseB0 + t);
                    b[0][0] = q0; b[0][1] = q2; b[1][0] = q1; b[1][1] = q3;
                    LDMX4(q0, q1, q2, q3, baseB1 + t);
                    b[2][0] = q0; b[2][1] = q2; b[3][0] = q1; b[3][1] = q3;
                    LDMX4(q0, q1, q2, q3, baseB2 + t);
                    b[4][0] = q0; b[4][1] = q2; b[5][0] = q1; b[5][1] = q3;
                    LDMX4(q0, q1, q2, q3, baseB3 + t);
                    b[6][0] = q0; b[6][1] = q2; b[7][0] = q1; b[7][1] = q3;
                }
                #pragma unroll
                for (int mi = 0; mi < 2; mi++)
                    #pragma unroll
                    for (int ni = 0; ni < 8; ni++)
                        MMAF8(acc[mi][ni], a[mi], b[ni][0], b[ni][1]);
            }
            cs = (cs + 1) & 3;
        }

        // ---- fused hinge epilogue (dequant + mask) ----
        const int r0 = (tile >> 3) * 128;
        const int c0 = (tile & 7) * 256;
        float lsum = 0.f;
        #pragma unroll
        for (int mi = 0; mi < 2; mi++) {
            #pragma unroll
            for (int half = 0; half < 2; half++) {
                const int r = r0 + wm + mi * 16 + (lane >> 2) + half * 8;
                const float alpha = g_sa[r];
                const float base = 1.0f - g_gt[r];
                const int lb = __ldg(&label[r]);
                #pragma unroll
                for (int ni = 0; ni < 8; ni++) {
                    const int cb = c0 + wn + ni * 8 + (lane & 3) * 2;
                    const int cls0 = g_tcs[cb], cls1 = g_tcs[cb + 1];
                    const float ab0 = alpha * g_sb[cb];
                    const float ab1 = alpha * g_sb[cb + 1];
                    if (cls0 >= 0 && cls0 != lb)
                        lsum += fmaxf(fmaf(acc[mi][ni][half * 2 + 0], ab0, base), 0.f);
                    if (cls1 >= 0 && cls1 != lb)
                        lsum += fmaxf(fmaf(acc[mi][ni][half * 2 + 1], ab1, base), 0.f);
                    acc[mi][ni][half * 2 + 0] = 0.f;
                    acc[mi][ni][half * 2 + 1] = 0.f;
                }
            }
        }
        #pragma unroll
        for (int o = 16; o > 0; o >>= 1) lsum += __shfl_down_sync(0xffffffffu, lsum, o);
        float* red = (float*)(smem + RED_OFF);
        if (lane == 0) red[wid] = lsum;
        __syncthreads();
        if (tid < 16) {
            float v = red[tid];
            #pragma unroll
            for (int o = 8; o > 0; o >>= 1) v += __shfl_down_sync(0xffffu, v, o);
            if (tid == 0) g_partial[tile] = v;
        }
        __syncthreads();
    }

    // ---- last CTA: deterministic final reduction ----
    float* red = (float*)(smem + RED_OFF);
    __threadfence();
    if (tid == 0) {
        unsigned v = atomicAdd(&g_done, 1u);
        ((unsigned*)red)[0] = (v == (unsigned)gridDim.x - 1u) ? 1u : 0u;
    }
    __syncthreads();
    if (((unsigned*)red)[0]) {
        float s = 0.f;
        for (int i = tid; i < nt; i += 512) s += g_partial[i];
        __syncthreads();
        red[tid] = s;
        __syncthreads();
        #pragma unroll
        for (int o = 256; o > 0; o >>= 1) {
            if (tid < o) red[tid] += red[tid + o];
            __syncthreads();
        }
        if (tid == 0) out[0] = red[0];
    }
}

extern "C" void kernel_launch(void* const* d_in, const int* in_sizes, int n_in,
                              void* d_out, int out_size) {
    const float* pred   = (const float*)d_in[0];
    const int*   label  = (const int*)d_in[1];
    const int*   tclass = (const int*)d_in[2];
    const float* sig    = (const float*)d_in[3];
    float* out = (float*)d_out;

    const int B = in_sizes[1];
    const int C = in_sizes[2];

    {
        dim3 tg((C + 31) / 32, DDIM / 32);
        transpose_sig_kernel<<<tg, 256>>>(sig, C);
    }
    prep_all_kernel<<<B / 8 + CPAD / 8, 256>>>(pred, label, tclass, B, C);

    const int nt = (CPAD / 256) * (B / 128);
    cudaFuncSetAttribute(hinge_mma_kernel, cudaFuncAttributeMaxDynamicSharedMemorySize, SMEM_TOTAL);
    hinge_mma_kernel<<<PGRID, 512, SMEM_TOTAL>>>(label, nt, out);
}

// round 14
// speedup vs baseline: 1.1552x; 1.1552x over previous
#include <cuda_runtime.h>
#include <cuda_bf16.h>
#include <cstdint>

// ============================================================
// RankingLoss megakernel: phase0 sig-transpose, phase1 prep
// (pred->bf16 + exact gt + gathered sig->bf16), phase2 persistent
// bf16 mma.sync GEMM + fused hinge + in-kernel final reduce.
// Grid = 148 CTAs x 512 thr (1 CTA/SM, co-resident) with
// software grid barriers between phases.
// ============================================================

#define MAX_B   16384
#define DDIM    256
#define CPAD    2048
#define PGRID   148
#define NWARPS_G (PGRID * 16)

__device__ float g_gt[MAX_B];
__device__ float g_partial[CPAD];
__device__ float g_sigT[CPAD * DDIM];             // sig^T fp32 [c][d]
__device__ __nv_bfloat16 g_predb[MAX_B * DDIM];   // pred bf16 [b][d]
__device__ __nv_bfloat16 g_sgath[CPAD * DDIM];    // gathered sig bf16 [c][d]
__device__ int g_tcs[CPAD];                        // class ids (-1 pad)
__device__ unsigned g_done;
__device__ unsigned g_bar;

// ---------------- SMEM layout ----------------
// GEMM ring: 4 slots x 48KB (A 16KB + B 32KB). Phase0 staging reuses slot 0.
#define SLOT_SZ  49152
#define B_SUB    16384
#define RED_OFF  196608
#define SMEM_TOTAL 198656

__device__ __forceinline__ uint32_t smem_u32(const void* p) {
    uint32_t a;
    asm("{ .reg .u64 t; cvta.to.shared.u64 t, %1; cvt.u32.u64 %0, t; }" : "=r"(a) : "l"(p));
    return a;
}

#define CP_ASYNC16(dst, src) \
    asm volatile("cp.async.cg.shared.global [%0], [%1], 16;" :: "r"(dst), "l"(src) : "memory")
#define CP_COMMIT() asm volatile("cp.async.commit_group;" ::: "memory")
#define CP_WAIT2()  asm volatile("cp.async.wait_group 2;" ::: "memory")

#define LDMX4(r0, r1, r2, r3, a) \
    asm volatile("ldmatrix.sync.aligned.m8n8.x4.shared.b16 {%0,%1,%2,%3}, [%4];" \
        : "=r"(r0), "=r"(r1), "=r"(r2), "=r"(r3) : "r"(a))

#define MMA16816(c, A, b0, b1) \
    asm volatile("mma.sync.aligned.m16n8k16.row.col.f32.bf16.bf16.f32 " \
        "{%0,%1,%2,%3}, {%4,%5,%6,%7}, {%8,%9}, {%0,%1,%2,%3};" \
        : "+f"((c)[0]), "+f"((c)[1]), "+f"((c)[2]), "+f"((c)[3]) \
        : "r"((A)[0]), "r"((A)[1]), "r"((A)[2]), "r"((A)[3]), "r"(b0), "r"(b1))

__device__ __forceinline__ void grid_barrier(unsigned target, int tid) {
    __syncthreads();
    __threadfence();
    if (tid == 0) {
        atomicAdd(&g_bar, 1u);
        while (atomicAdd(&g_bar, 0u) < target) { }
    }
    __syncthreads();
}

__device__ __forceinline__ uint4 cvt8_bf16(float4 a, float4 b) {
    __nv_bfloat162 o[4];
    o[0] = __nv_bfloat162(__float2bfloat16(a.x), __float2bfloat16(a.y));
    o[1] = __nv_bfloat162(__float2bfloat16(a.z), __float2bfloat16(a.w));
    o[2] = __nv_bfloat162(__float2bfloat16(b.x), __float2bfloat16(b.y));
    o[3] = __nv_bfloat162(__float2bfloat16(b.z), __float2bfloat16(b.w));
    return *(uint4*)o;
}

// Fill one 64-k chunk of tile (ft) into ring slot fc. 512 threads.
__device__ __forceinline__ void fill_chunk(uint32_t sb, int ft, int fc, int tid) {
    const int r0f = (ft >> 3) * 128;
    const int c0f = (ft & 7) * 256;
    const uint32_t slot = sb + (uint32_t)fc * SLOT_SZ;
    #pragma unroll
    for (int i = 0; i < 2; i++) {              // A: 128 rows x 8 units
        int op = tid + i * 512;
        int row = op >> 3, u = op & 7;
        uint32_t dst = slot + (uint32_t)row * 128u + (uint32_t)((u ^ (row & 7)) << 4);
        size_t src = __cvta_generic_to_global(&g_predb[(size_t)(r0f + row) * DDIM + fc * 64 + u * 8]);
        CP_ASYNC16(dst, src);
    }
    #pragma unroll
    for (int i = 0; i < 4; i++) {              // B: 256 rows x 8 units
        int op = tid + i * 512;
        int row = op >> 3, u = op & 7;
        uint32_t dst = slot + B_SUB + (uint32_t)row * 128u + (uint32_t)((u ^ (row & 7)) << 4);
        size_t src = __cvta_generic_to_global(&g_sgath[(size_t)(c0f + row) * DDIM + fc * 64 + u * 8]);
        CP_ASYNC16(dst, src);
    }
}

__global__ __launch_bounds__(512, 1)
void ranking_mega_kernel(const float* __restrict__ pred,
                         const int* __restrict__ label,
                         const int* __restrict__ tclass,
                         const float* __restrict__ sig,
                         int B, int C, int nt,
                         float* __restrict__ out) {
    extern __shared__ char smem[];
    const uint32_t sb = smem_u32(smem);
    const int tid = threadIdx.x, lane = tid & 31, wid = tid >> 5;
    const int bid = blockIdx.x;

    // ================= Phase 0: transpose sig [d][c] -> sigT [c][d] =================
    // 32x32 tiles; 63 c-tiles x 8 d-tiles = 504 tiles; 2 halves per CTA; 2 fixed iters.
    {
        const int half = tid >> 8;             // 0 or 1
        const int st = tid & 255;
        const int tx = st & 31, ty = (st >> 5); // ty 0..7
        float* tp = (float*)(smem + half * 4352);
        const int ntC = (C + 31) >> 5;         // 63
        #pragma unroll
        for (int it = 0; it < 2; it++) {
            int slot = bid * 2 + half + it * (PGRID * 2);
            bool act = slot < ntC * 8;
            int cb = (slot % ntC) * 32;
            int db = (slot / ntC) * 32;
            if (act) {
                #pragma unroll
                for (int i = 0; i < 4; i++) {
                    int d = db + ty + i * 8, c = cb + tx;
                    tp[(ty + i * 8) * 33 + tx] = (c < C) ? sig[(size_t)d * C + c] : 0.f;
                }
            }
            __syncthreads();
            if (act) {
                #pragma unroll
                for (int i = 0; i < 4; i++) {
                    int c = cb + ty + i * 8, d = db + tx;
                    if (c < C) g_sigT[(size_t)c * DDIM + d] = tp[tx * 33 + (ty + i * 8)];
                }
            }
            __syncthreads();
        }
    }
    grid_barrier(PGRID, tid);

    // ================= Phase 1: prep rows (pred->bf16 + gt) and classes =================
    {
        const int w = bid * 16 + wid;          // global warp id, 0..2367
        for (int b = w; b < B; b += NWARPS_G) {
            const float4* p4 = (const float4*)pred + (size_t)b * 64;
            float4 v0 = p4[lane * 2], v1 = p4[lane * 2 + 1];
            *(uint4*)&g_predb[(size_t)b * DDIM + lane * 8] = cvt8_bf16(v0, v1);
            int lb = label[b];
            const float4* s4 = (const float4*)g_sigT + (size_t)lb * 64;
            float4 c0 = s4[lane * 2], c1 = s4[lane * 2 + 1];
            float s = v0.x*c0.x + v0.y*c0.y + v0.z*c0.z + v0.w*c0.w
                    + v1.x*c1.x + v1.y*c1.y + v1.z*c1.z + v1.w*c1.w;
            #pragma unroll
            for (int o = 16; o > 0; o >>= 1) s += __shfl_down_sync(0xffffffffu, s, o);
            if (lane == 0) g_gt[b] = s;
        }
        for (int c = w; c < CPAD; c += NWARPS_G) {
            if (c < C) {
                int cls = tclass[c];
                const float4* s4 = (const float4*)g_sigT + (size_t)cls * 64;
                float4 v0 = s4[lane * 2], v1 = s4[lane * 2 + 1];
                *(uint4*)&g_sgath[(size_t)c * DDIM + lane * 8] = cvt8_bf16(v0, v1);
                if (lane == 0) g_tcs[c] = cls;
            } else {
                uint4 z; z.x = z.y = z.z = z.w = 0u;
                *(uint4*)&g_sgath[(size_t)c * DDIM + lane * 8] = z;
                if (lane == 0) g_tcs[c] = -1;
            }
        }
    }
    grid_barrier(2 * PGRID, tid);

    // ================= Phase 2: persistent bf16 GEMM + hinge =================
    const int wm = (wid & 3) * 32;             // warp 32 rows
    const int wn = (wid >> 2) * 64;            // warp 64 cols
    const int lrow = lane & 15;
    const uint32_t u0 = (uint32_t)(lane >> 4);
    const uint32_t xr = (uint32_t)(lane & 7);

    float acc[2][8][4];
    #pragma unroll
    for (int mi = 0; mi < 2; mi++)
        #pragma unroll
        for (int ni = 0; ni < 8; ni++)
            #pragma unroll
            for (int q = 0; q < 4; q++) acc[mi][ni][q] = 0.f;

    int ft = bid, fc = 0;
    #pragma unroll
    for (int p = 0; p < 3; p++) {
        if (ft < nt) fill_chunk(sb, ft, fc, tid);
        CP_COMMIT();
        if (++fc == 4) { fc = 0; ft += PGRID; }
    }

    for (int tile = bid; tile < nt; tile += PGRID) {
        #pragma unroll
        for (int ch = 0; ch < 4; ch++) {
            CP_WAIT2();
            __syncthreads();
            if (ft < nt) fill_chunk(sb, ft, fc, tid);
            CP_COMMIT();
            if (++fc == 4) { fc = 0; ft += PGRID; }
            const uint32_t slot = sb + (uint32_t)ch * SLOT_SZ;
            uint32_t baseA0 = slot + (uint32_t)(wm + lrow) * 128u;
            uint32_t baseA1 = baseA0 + 16u * 128u;
            uint32_t baseB0 = slot + B_SUB + (uint32_t)(wn + lrow) * 128u;
            uint32_t baseB1 = baseB0 + 16u * 128u;
            uint32_t baseB2 = baseB0 + 32u * 128u;
            uint32_t baseB3 = baseB0 + 48u * 128u;
            #pragma unroll
            for (int kk = 0; kk < 4; kk++) {
                const uint32_t t = (((uint32_t)(2 * kk) + u0) ^ xr) << 4;
                uint32_t a[2][4];
                LDMX4(a[0][0], a[0][1], a[0][2], a[0][3], baseA0 + t);
                LDMX4(a[1][0], a[1][1], a[1][2], a[1][3], baseA1 + t);
                uint32_t b[8][2];
                {
                    uint32_t q0, q1, q2, q3;
                    LDMX4(q0, q1, q2, q3, baseB0 + t);
                    b[0][0] = q0; b[0][1] = q2; b[1][0] = q1; b[1][1] = q3;
                    LDMX4(q0, q1, q2, q3, baseB1 + t);
                    b[2][0] = q0; b[2][1] = q2; b[3][0] = q1; b[3][1] = q3;
                    LDMX4(q0, q1, q2, q3, baseB2 + t);
                    b[4][0] = q0; b[4][1] = q2; b[5][0] = q1; b[5][1] = q3;
                    LDMX4(q0, q1, q2, q3, baseB3 + t);
                    b[6][0] = q0; b[6][1] = q2; b[7][0] = q1; b[7][1] = q3;
                }
                #pragma unroll
                for (int mi = 0; mi < 2; mi++)
                    #pragma unroll
                    for (int ni = 0; ni < 8; ni++)
                        MMA16816(acc[mi][ni], a[mi], b[ni][0], b[ni][1]);
            }
        }

        const int r0 = (tile >> 3) * 128;
        const int c0 = (tile & 7) * 256;
        float lsum = 0.f;
        #pragma unroll
        for (int mi = 0; mi < 2; mi++) {
            #pragma unroll
            for (int half = 0; half < 2; half++) {
                const int r = r0 + wm + mi * 16 + (lane >> 2) + half * 8;
                const float base = 1.0f - g_gt[r];
                const int lb = __ldg(&label[r]);
                #pragma unroll
                for (int ni = 0; ni < 8; ni++) {
                    const int cb = c0 + wn + ni * 8 + (lane & 3) * 2;
                    const int cls0 = g_tcs[cb], cls1 = g_tcs[cb + 1];
                    if (cls0 >= 0 && cls0 != lb)
                        lsum += fmaxf(acc[mi][ni][half * 2 + 0] + base, 0.f);
                    if (cls1 >= 0 && cls1 != lb)
                        lsum += fmaxf(acc[mi][ni][half * 2 + 1] + base, 0.f);
                    acc[mi][ni][half * 2 + 0] = 0.f;
                    acc[mi][ni][half * 2 + 1] = 0.f;
                }
            }
        }
        #pragma unroll
        for (int o = 16; o > 0; o >>= 1) lsum += __shfl_down_sync(0xffffffffu, lsum, o);
        float* red = (float*)(smem + RED_OFF);
        if (lane == 0) red[wid] = lsum;
        __syncthreads();
        if (tid < 16) {
            float v = red[tid];
            #pragma unroll
            for (int o = 8; o > 0; o >>= 1) v += __shfl_down_sync(0xffffu, v, o);
            if (tid == 0) g_partial[tile] = v;
        }
        __syncthreads();
    }

    // ---- last CTA: deterministic final reduction + counter reset ----
    float* red = (float*)(smem + RED_OFF);
    __threadfence();
    if (tid == 0) {
        unsigned v = atomicAdd(&g_done, 1u);
        ((unsigned*)red)[0] = (v == (unsigned)gridDim.x - 1u) ? 1u : 0u;
    }
    __syncthreads();
    if (((unsigned*)red)[0]) {
        float s = 0.f;
        for (int i = tid; i < nt; i += 512) s += g_partial[i];
        __syncthreads();
        red[tid] = s;
        __syncthreads();
        #pragma unroll
        for (int o = 256; o > 0; o >>= 1) {
            if (tid < o) red[tid] += red[tid + o];
            __syncthreads();
        }
        if (tid == 0) {
            out[0] = red[0];
            g_done = 0u;          // reset for next graph replay
            g_bar = 0u;
        }
    }
}

extern "C" void kernel_launch(void* const* d_in, const int* in_sizes, int n_in,
                              void* d_out, int out_size) {
    const float* pred   = (const float*)d_in[0];
    const int*   label  = (const int*)d_in[1];
    const int*   tclass = (const int*)d_in[2];
    const float* sig    = (const float*)d_in[3];
    float* out = (float*)d_out;

    const int B = in_sizes[1];
    const int C = in_sizes[2];
    const int nt = (CPAD / 256) * (B / 128);

    cudaFuncSetAttribute(ranking_mega_kernel, cudaFuncAttributeMaxDynamicSharedMemorySize, SMEM_TOTAL);
    ranking_mega_kernel<<<PGRID, 512, SMEM_TOTAL>>>(pred, label, tclass, sig, B, C, nt, out);
}

// round 15
// speedup vs baseline: 1.1835x; 1.0245x over previous
#include <cuda_runtime.h>
#include <cuda_bf16.h>
#include <cstdint>

// ============================================================
// RankingLoss: persistent bf16 mma.sync GEMM, 1024-thread CTAs
// (32 warps, 8 warps/SMSP) with 16x64 warp tiles, cp.async ring,
// fused hinge epilogue + in-kernel final reduce.
// loss = sum_{b,c: tc[c]!=label[b]} max(1 + pred_b·sigc_c - gt_b, 0)
// ============================================================

#define MAX_B   16384
#define DDIM    256
#define CPAD    2048
#define PGRID   148

__device__ float g_gt[MAX_B];
__device__ float g_partial[CPAD];
__device__ float g_sigT[CPAD * DDIM];             // sig^T fp32 [c][d]
__device__ __nv_bfloat16 g_predb[MAX_B * DDIM];   // pred bf16 [b][d]
__device__ __nv_bfloat16 g_sgath[CPAD * DDIM];    // gathered sig bf16 [c][d]
__device__ int g_tcs[CPAD];                        // class ids (-1 pad)
__device__ unsigned g_done;

// ---------------- transpose sig fp32: [d][c] -> [c][d] ----------------
__global__ void transpose_sig_kernel(const float* __restrict__ sig, int C) {
    __shared__ float t[32][33];
    int cb = blockIdx.x * 32, db = blockIdx.y * 32;
    int tx = threadIdx.x & 31, ty = threadIdx.x >> 5;
    #pragma unroll
    for (int i = 0; i < 32; i += 8) {
        int d = db + ty + i, c = cb + tx;
        t[ty + i][tx] = (c < C) ? sig[(size_t)d * C + c] : 0.f;
    }
    __syncthreads();
    #pragma unroll
    for (int i = 0; i < 32; i += 8) {
        int c = cb + ty + i, d = db + tx;
        if (c < CPAD) g_sigT[(size_t)c * DDIM + d] = t[tx][ty + i];
    }
    if (blockIdx.x == 0 && blockIdx.y == 0 && threadIdx.x == 0) g_done = 0u;
}

// ---------------- fused prep: pred->bf16 + gt (rows); gathered sig->bf16 (classes) ----------------
__device__ __forceinline__ uint4 cvt8_bf16(float4 a, float4 b) {
    __nv_bfloat162 o[4];
    o[0] = __nv_bfloat162(__float2bfloat16(a.x), __float2bfloat16(a.y));
    o[1] = __nv_bfloat162(__float2bfloat16(a.z), __float2bfloat16(a.w));
    o[2] = __nv_bfloat162(__float2bfloat16(b.x), __float2bfloat16(b.y));
    o[3] = __nv_bfloat162(__float2bfloat16(b.z), __float2bfloat16(b.w));
    return *(uint4*)o;
}

__global__ void prep_all_kernel(const float* __restrict__ pred,
                                const int* __restrict__ label,
                                const int* __restrict__ tclass,
                                int B, int C) {
    const int tid = threadIdx.x, lane = tid & 31, wid = tid >> 5;
    const int rowBlocks = B / 8;

    if ((int)blockIdx.x < rowBlocks) {
        int b = blockIdx.x * 8 + wid;
        const float4* p4 = (const float4*)pred + (size_t)b * 64;
        float4 v0 = p4[lane * 2], v1 = p4[lane * 2 + 1];
        *(uint4*)&g_predb[(size_t)b * DDIM + lane * 8] = cvt8_bf16(v0, v1);
        int lb = label[b];
        const float4* s4 = (const float4*)g_sigT + (size_t)lb * 64;
        float4 c0 = s4[lane * 2], c1 = s4[lane * 2 + 1];
        float s = v0.x*c0.x + v0.y*c0.y + v0.z*c0.z + v0.w*c0.w
                + v1.x*c1.x + v1.y*c1.y + v1.z*c1.z + v1.w*c1.w;
        #pragma unroll
        for (int o = 16; o > 0; o >>= 1) s += __shfl_down_sync(0xffffffffu, s, o);
        if (lane == 0) g_gt[b] = s;
    } else {
        int c = ((int)blockIdx.x - rowBlocks) * 8 + wid;
        if (c < C) {
            int cls = tclass[c];
            const float4* s4 = (const float4*)g_sigT + (size_t)cls * 64;
            float4 v0 = s4[lane * 2], v1 = s4[lane * 2 + 1];
            *(uint4*)&g_sgath[(size_t)c * DDIM + lane * 8] = cvt8_bf16(v0, v1);
            if (lane == 0) g_tcs[c] = cls;
        } else if (c < CPAD) {
            uint4 z; z.x = z.y = z.z = z.w = 0u;
            *(uint4*)&g_sgath[(size_t)c * DDIM + lane * 8] = z;
            if (lane == 0) g_tcs[c] = -1;
        }
    }
}

// ---------------- persistent fused MMA GEMM + hinge + final reduce ----------------
// Tile: 128 rows x 256 classes. 1024 threads (32 warps, 8m x 4n, warp 16x64).
// Ring: 4 slots x (A 16KB + B 32KB) = 192KB.
#define SLOT_SZ  49152
#define B_SUB    16384
#define RED_OFF  196608
#define SMEM_TOTAL 200704

__device__ __forceinline__ uint32_t smem_u32(const void* p) {
    uint32_t a;
    asm("{ .reg .u64 t; cvta.to.shared.u64 t, %1; cvt.u32.u64 %0, t; }" : "=r"(a) : "l"(p));
    return a;
}

#define CP_ASYNC16(dst, src) \
    asm volatile("cp.async.cg.shared.global [%0], [%1], 16;" :: "r"(dst), "l"(src) : "memory")
#define CP_COMMIT() asm volatile("cp.async.commit_group;" ::: "memory")
#define CP_WAIT2()  asm volatile("cp.async.wait_group 2;" ::: "memory")

#define LDMX4(r0, r1, r2, r3, a) \
    asm volatile("ldmatrix.sync.aligned.m8n8.x4.shared.b16 {%0,%1,%2,%3}, [%4];" \
        : "=r"(r0), "=r"(r1), "=r"(r2), "=r"(r3) : "r"(a))

#define MMA16816(c, A, b0, b1) \
    asm volatile("mma.sync.aligned.m16n8k16.row.col.f32.bf16.bf16.f32 " \
        "{%0,%1,%2,%3}, {%4,%5,%6,%7}, {%8,%9}, {%0,%1,%2,%3};" \
        : "+f"((c)[0]), "+f"((c)[1]), "+f"((c)[2]), "+f"((c)[3]) \
        : "r"((A)[0]), "r"((A)[1]), "r"((A)[2]), "r"((A)[3]), "r"(b0), "r"(b1))

// Fill one 64-k chunk of tile (ft) into ring slot fc. 1024 threads.
__device__ __forceinline__ void fill_chunk(uint32_t sb, int ft, int fc, int tid) {
    const int r0f = (ft >> 3) * 128;
    const int c0f = (ft & 7) * 256;
    const uint32_t slot = sb + (uint32_t)fc * SLOT_SZ;
    {   // A: 128 rows x 8 units = 1024 ops
        int row = tid >> 3, u = tid & 7;
        uint32_t dst = slot + (uint32_t)row * 128u + (uint32_t)((u ^ (row & 7)) << 4);
        size_t src = __cvta_generic_to_global(&g_predb[(size_t)(r0f + row) * DDIM + fc * 64 + u * 8]);
        CP_ASYNC16(dst, src);
    }
    #pragma unroll
    for (int i = 0; i < 2; i++) {              // B: 256 rows x 8 units = 2048 ops
        int op = tid + i * 1024;
        int row = op >> 3, u = op & 7;
        uint32_t dst = slot + B_SUB + (uint32_t)row * 128u + (uint32_t)((u ^ (row & 7)) << 4);
        size_t src = __cvta_generic_to_global(&g_sgath[(size_t)(c0f + row) * DDIM + fc * 64 + u * 8]);
        CP_ASYNC16(dst, src);
    }
}

__global__ __launch_bounds__(1024, 1)
void hinge_mma_kernel(const int* __restrict__ label, int nt, float* __restrict__ out) {
    extern __shared__ char smem[];
    const uint32_t sb = smem_u32(smem);
    const int tid = threadIdx.x, lane = tid & 31, wid = tid >> 5;
    const int bid = blockIdx.x;

    const int wm = (wid & 7) * 16;             // warp 16 rows
    const int wn = (wid >> 3) * 64;            // warp 64 cols
    const int lrow = lane & 15;
    const uint32_t u0 = (uint32_t)(lane >> 4);
    const uint32_t xr = (uint32_t)(lane & 7);

    float acc[8][4];
    #pragma unroll
    for (int ni = 0; ni < 8; ni++)
        #pragma unroll
        for (int q = 0; q < 4; q++) acc[ni][q] = 0.f;

    // ---- pipeline prologue: fill 3 chunks ahead ----
    int ft = bid, fc = 0;
    #pragma unroll
    for (int p = 0; p < 3; p++) {
        if (ft < nt) fill_chunk(sb, ft, fc, tid);
        CP_COMMIT();
        if (++fc == 4) { fc = 0; ft += PGRID; }
    }

    for (int tile = bid; tile < nt; tile += PGRID) {
        #pragma unroll
        for (int ch = 0; ch < 4; ch++) {
            CP_WAIT2();
            __syncthreads();
            if (ft < nt) fill_chunk(sb, ft, fc, tid);
            CP_COMMIT();
            if (++fc == 4) { fc = 0; ft += PGRID; }
            // ---- MMA on chunk ch (4 k-steps) ----
            const uint32_t slot = sb + (uint32_t)ch * SLOT_SZ;
            const uint32_t baseA = slot + (uint32_t)(wm + lrow) * 128u;
            const uint32_t baseB = slot + B_SUB + (uint32_t)(wn + lrow) * 128u;
            #pragma unroll
            for (int kk = 0; kk < 4; kk++) {
                const uint32_t t = (((uint32_t)(2 * kk) + u0) ^ xr) << 4;
                uint32_t a[4];
                LDMX4(a[0], a[1], a[2], a[3], baseA + t);
                #pragma unroll
                for (int p = 0; p < 4; p++) {
                    uint32_t q0, q1, q2, q3;
                    LDMX4(q0, q1, q2, q3, baseB + (uint32_t)p * 2048u + t);
                    MMA16816(acc[2 * p], a, q0, q2);
                    MMA16816(acc[2 * p + 1], a, q1, q3);
                }
            }
        }

        // ---- fused hinge epilogue ----
        const int r0 = (tile >> 3) * 128;
        const int c0 = (tile & 7) * 256;
        float lsum = 0.f;
        #pragma unroll
        for (int half = 0; half < 2; half++) {
            const int r = r0 + wm + (lane >> 2) + half * 8;
            const float base = 1.0f - g_gt[r];
            const int lb = __ldg(&label[r]);
            #pragma unroll
            for (int ni = 0; ni < 8; ni++) {
                const int cb = c0 + wn + ni * 8 + (lane & 3) * 2;
                const int cls0 = g_tcs[cb], cls1 = g_tcs[cb + 1];
                if (cls0 >= 0 && cls0 != lb)
                    lsum += fmaxf(acc[ni][half * 2 + 0] + base, 0.f);
                if (cls1 >= 0 && cls1 != lb)
                    lsum += fmaxf(acc[ni][half * 2 + 1] + base, 0.f);
                acc[ni][half * 2 + 0] = 0.f;
                acc[ni][half * 2 + 1] = 0.f;
            }
        }
        #pragma unroll
        for (int o = 16; o > 0; o >>= 1) lsum += __shfl_down_sync(0xffffffffu, lsum, o);
        float* red = (float*)(smem + RED_OFF);
        if (lane == 0) red[wid] = lsum;
        __syncthreads();
        if (tid < 32) {
            float v = red[tid];
            #pragma unroll
            for (int o = 16; o > 0; o >>= 1) v += __shfl_down_sync(0xffffffffu, v, o);
            if (tid == 0) g_partial[tile] = v;
        }
        __syncthreads();
    }

    // ---- last CTA: deterministic final reduction ----
    float* red = (float*)(smem + RED_OFF);
    __threadfence();
    if (tid == 0) {
        unsigned v = atomicAdd(&g_done, 1u);
        ((unsigned*)red)[0] = (v == (unsigned)gridDim.x - 1u) ? 1u : 0u;
    }
    __syncthreads();
    if (((unsigned*)red)[0]) {
        float s = 0.f;
        for (int i = tid; i < nt; i += 1024) s += g_partial[i];
        __syncthreads();
        red[tid] = s;
        __syncthreads();
        #pragma unroll
        for (int o = 512; o > 0; o >>= 1) {
            if (tid < o) red[tid] += red[tid + o];
            __syncthreads();
        }
        if (tid == 0) out[0] = red[0];
    }
}

extern "C" void kernel_launch(void* const* d_in, const int* in_sizes, int n_in,
                              void* d_out, int out_size) {
    const float* pred   = (const float*)d_in[0];
    const int*   label  = (const int*)d_in[1];
    const int*   tclass = (const int*)d_in[2];
    const float* sig    = (const float*)d_in[3];
    float* out = (float*)d_out;

    const int B = in_sizes[1];
    const int C = in_sizes[2];

    {
        dim3 tg((C + 31) / 32, DDIM / 32);
        transpose_sig_kernel<<<tg, 256>>>(sig, C);
    }
    prep_all_kernel<<<B / 8 + CPAD / 8, 256>>>(pred, label, tclass, B, C);

    const int nt = (CPAD / 256) * (B / 128);
    cudaFuncSetAttribute(hinge_mma_kernel, cudaFuncAttributeMaxDynamicSharedMemorySize, SMEM_TOTAL);
    hinge_mma_kernel<<<PGRID, 1024, SMEM_TOTAL>>>(label, nt, out);
}